// round 2
// baseline (speedup 1.0000x reference)
#include <cuda_runtime.h>
#include <cstdint>

#define S_DIM 1024
#define G_DIM 10
#define F_DIM 5
#define B_DIM 8
#define C_DIM 3
#define KW (2 * F_DIM + 1)   // 11

// Smoothed, scaled, clipped offset field: [B, 2, G, G]
__device__ float g_field[B_DIM * 2 * G_DIM * G_DIM];

// ---------------------------------------------------------------------------
// Kernel 1: 11x11 gaussian conv (edge padding) on the 10x10 offset grids,
// then scale by max_offset and clip to [-max_offset, max_offset].
// 1600 threads total — negligible cost.
// ---------------------------------------------------------------------------
__global__ void smooth_kernel(const float* __restrict__ off_x,
                              const float* __restrict__ off_y,
                              const float* __restrict__ weight,
                              const void* __restrict__ max_move_ptr) {
    int idx = blockIdx.x * blockDim.x + threadIdx.x;
    if (idx >= B_DIM * 2 * G_DIM * G_DIM) return;

    // Decode max_move scalar (int32 or float32)
    unsigned u = *(const unsigned*)max_move_ptr;
    int as_int = (int)u;
    float mm = (as_int >= -1000000 && as_int <= 1000000) ? (float)as_int
                                                         : __int_as_float(as_int);
    float max_offset = 2.0f * mm / (float)S_DIM;

    int j  = idx % G_DIM;
    int i  = (idx / G_DIM) % G_DIM;
    int ch = (idx / (G_DIM * G_DIM)) % 2;
    int b  = idx / (2 * G_DIM * G_DIM);

    const float* src = (ch == 0 ? off_x : off_y) + b * G_DIM * G_DIM;

    float acc = 0.0f;
#pragma unroll
    for (int ki = 0; ki < KW; ki++) {
        int pi = i + ki - F_DIM;
        pi = min(max(pi, 0), G_DIM - 1);
#pragma unroll
        for (int kj = 0; kj < KW; kj++) {
            int pj = j + kj - F_DIM;
            pj = min(max(pj, 0), G_DIM - 1);
            acc += src[pi * G_DIM + pj] * weight[ki * KW + kj];
        }
    }
    acc *= max_offset;
    acc = fminf(fmaxf(acc, -max_offset), max_offset);
    g_field[idx] = acc;
}

// Axis mapping for the G->S bilinear upsample (matches reference exactly)
__device__ __forceinline__ void axis_map(int p, int& i0, int& i1, float& w) {
    float src = fmaxf(((float)p + 0.5f) * ((float)G_DIM / (float)S_DIM) - 0.5f, 0.0f);
    float fl = floorf(src);
    i0 = min((int)fl, G_DIM - 1);
    i1 = min(i0 + 1, G_DIM - 1);
    w = src - (float)i0;
}

// ---------------------------------------------------------------------------
// Kernel 2: fused upsample + grid construction + bilinear grid_sample.
// One thread per output (b, y, x); reuses grid coords across all 3 channels.
// grid: (S/256, S, B); block: 256.
// ---------------------------------------------------------------------------
__global__ __launch_bounds__(256)
void deform_kernel(const float* __restrict__ xin, float* __restrict__ out) {
    const int b  = blockIdx.z;
    const int y  = blockIdx.y;
    const int xc = blockIdx.x * blockDim.x + threadIdx.x;

    __shared__ float gsx[G_DIM * G_DIM];
    __shared__ float gsy[G_DIM * G_DIM];
    if (threadIdx.x < G_DIM * G_DIM) {
        gsx[threadIdx.x] = g_field[(b * 2 + 0) * G_DIM * G_DIM + threadIdx.x];
        gsy[threadIdx.x] = g_field[(b * 2 + 1) * G_DIM * G_DIM + threadIdx.x];
    }
    __syncthreads();

    if (xc >= S_DIM) return;

    // Upsample coordinates
    int ry0, ry1, rx0, rx1;
    float wry, wrx;
    axis_map(y, ry0, ry1, wry);
    axis_map(xc, rx0, rx1, wrx);

    float w00 = (1.0f - wry) * (1.0f - wrx);
    float w01 = (1.0f - wry) * wrx;
    float w10 = wry * (1.0f - wrx);
    float w11 = wry * wrx;

    float gx = gsx[ry0 * G_DIM + rx0] * w00 + gsx[ry0 * G_DIM + rx1] * w01 +
               gsx[ry1 * G_DIM + rx0] * w10 + gsx[ry1 * G_DIM + rx1] * w11;
    float gy = gsy[ry0 * G_DIM + rx0] * w00 + gsy[ry0 * G_DIM + rx1] * w01 +
               gsy[ry1 * G_DIM + rx0] * w10 + gsy[ry1 * G_DIM + rx1] * w11;

    // Base grid P (channel 0 = x over columns, channel 1 = y over rows)
    float lin_x = ((float)xc / (float)(S_DIM - 1)) * 2.0f - 1.0f;
    float lin_y = ((float)y  / (float)(S_DIM - 1)) * 2.0f - 1.0f;

    float grid_x = fminf(fmaxf(gx + lin_x, -1.0f), 1.0f);
    float grid_y = fminf(fmaxf(gy + lin_y, -1.0f), 1.0f);

    // grid_sample source coordinates (align_corners=False convention per ref)
    float ix = ((grid_x + 1.0f) * (float)S_DIM - 1.0f) * 0.5f;
    float iy = ((grid_y + 1.0f) * (float)S_DIM - 1.0f) * 0.5f;

    int x0 = (int)floorf(ix);
    int x1 = x0 + 1;
    int y0 = (int)floorf(iy);
    int y1 = y0 + 1;
    float wx = ix - (float)x0;
    float wy = iy - (float)y0;

    float m_x0 = (x0 >= 0 && x0 < S_DIM) ? 1.0f : 0.0f;
    float m_x1 = (x1 >= 0 && x1 < S_DIM) ? 1.0f : 0.0f;
    float m_y0 = (y0 >= 0 && y0 < S_DIM) ? 1.0f : 0.0f;
    float m_y1 = (y1 >= 0 && y1 < S_DIM) ? 1.0f : 0.0f;

    float cw00 = (1.0f - wy) * (1.0f - wx) * m_y0 * m_x0;
    float cw01 = (1.0f - wy) * wx          * m_y0 * m_x1;
    float cw10 = wy * (1.0f - wx)          * m_y1 * m_x0;
    float cw11 = wy * wx                   * m_y1 * m_x1;

    int cx0 = min(max(x0, 0), S_DIM - 1);
    int cx1 = min(max(x1, 0), S_DIM - 1);
    int cy0 = min(max(y0, 0), S_DIM - 1);
    int cy1 = min(max(y1, 0), S_DIM - 1);

    const size_t row0 = (size_t)cy0 * S_DIM;
    const size_t row1 = (size_t)cy1 * S_DIM;

#pragma unroll
    for (int c = 0; c < C_DIM; c++) {
        const float* img = xin + ((size_t)(b * C_DIM + c)) * S_DIM * S_DIM;
        float v = img[row0 + cx0] * cw00 + img[row0 + cx1] * cw01 +
                  img[row1 + cx0] * cw10 + img[row1 + cx1] * cw11;
        out[(((size_t)(b * C_DIM + c)) * S_DIM + y) * S_DIM + xc] = v;
    }
}

extern "C" void kernel_launch(void* const* d_in, const int* in_sizes, int n_in,
                              void* d_out, int out_size) {
    const float* x        = (const float*)d_in[0];
    const float* offset_x = (const float*)d_in[1];
    const float* offset_y = (const float*)d_in[2];
    const float* weight   = (const float*)d_in[3];
    const void*  max_move = d_in[4];

    float* out = (float*)d_out;

    smooth_kernel<<<(B_DIM * 2 * G_DIM * G_DIM + 127) / 128, 128>>>(
        offset_x, offset_y, weight, max_move);

    dim3 grid(S_DIM / 256, S_DIM, B_DIM);
    deform_kernel<<<grid, 256>>>(x, out);
}

// round 3
// speedup vs baseline: 1.0490x; 1.0490x over previous
#include <cuda_runtime.h>
#include <cstdint>

#define S_DIM 1024
#define G_DIM 10
#define F_DIM 5
#define B_DIM 8
#define C_DIM 3
#define KW (2 * F_DIM + 1)   // 11
#define PLANE (S_DIM * S_DIM)

// Smoothed, scaled, clipped offset field: [B, 2, G, G]
__device__ float g_field[B_DIM * 2 * G_DIM * G_DIM];

// ---------------------------------------------------------------------------
// Kernel 1: 11x11 gaussian conv (edge padding) on the 10x10 offset grids,
// then scale by max_offset and clip. 1600 threads — negligible.
// ---------------------------------------------------------------------------
__global__ void smooth_kernel(const float* __restrict__ off_x,
                              const float* __restrict__ off_y,
                              const float* __restrict__ weight,
                              const void* __restrict__ max_move_ptr) {
    int idx = blockIdx.x * blockDim.x + threadIdx.x;
    if (idx >= B_DIM * 2 * G_DIM * G_DIM) return;

    unsigned u = *(const unsigned*)max_move_ptr;
    int as_int = (int)u;
    float mm = (as_int >= -1000000 && as_int <= 1000000) ? (float)as_int
                                                         : __int_as_float(as_int);
    float max_offset = 2.0f * mm / (float)S_DIM;

    int j  = idx % G_DIM;
    int i  = (idx / G_DIM) % G_DIM;
    int ch = (idx / (G_DIM * G_DIM)) % 2;
    int b  = idx / (2 * G_DIM * G_DIM);

    const float* src = (ch == 0 ? off_x : off_y) + b * G_DIM * G_DIM;

    float acc = 0.0f;
#pragma unroll
    for (int ki = 0; ki < KW; ki++) {
        int pi = min(max(i + ki - F_DIM, 0), G_DIM - 1);
#pragma unroll
        for (int kj = 0; kj < KW; kj++) {
            int pj = min(max(j + kj - F_DIM, 0), G_DIM - 1);
            acc += src[pi * G_DIM + pj] * weight[ki * KW + kj];
        }
    }
    acc *= max_offset;
    acc = fminf(fmaxf(acc, -max_offset), max_offset);
    g_field[idx] = acc;
}

// ---------------------------------------------------------------------------
// Kernel 2: one block per (y, b) output row; 256 threads x 4 pixels each.
// Field y-interpolation hoisted to shared row buffers; float4 stores.
// ---------------------------------------------------------------------------
__global__ __launch_bounds__(256)
void deform_kernel(const float* __restrict__ xin, float* __restrict__ out) {
    const int y = blockIdx.x;
    const int b = blockIdx.y;

    __shared__ float rowx[G_DIM];
    __shared__ float rowy[G_DIM];

    // y-axis upsample map (block-uniform): src = max((y+0.5)*G/S - 0.5, 0)
    const float AXC = (float)G_DIM / (float)S_DIM;            // 0.009765625
    const float AXB = 0.5f * AXC - 0.5f;                      // -0.4951171875
    float fy = fmaxf(fmaf((float)y, AXC, AXB), 0.0f);
    int   ry0 = (int)fy;                 // fy >= 0, floor == trunc; max 9
    float wry = fy - (float)ry0;
    int   ry1 = min(ry0 + 1, G_DIM - 1);

    if (threadIdx.x < 2 * G_DIM) {
        int ch  = threadIdx.x / G_DIM;
        int col = threadIdx.x - ch * G_DIM;
        const float* f = g_field + (b * 2 + ch) * G_DIM * G_DIM;
        float v0 = f[ry0 * G_DIM + col];
        float v1 = f[ry1 * G_DIM + col];
        float v  = fmaf(wry, v1 - v0, v0);
        (ch == 0 ? rowx : rowy)[col] = v;
    }
    __syncthreads();

    const float lin_y = fmaf((float)y, 2.0f / (float)(S_DIM - 1), -1.0f);

    const float* img0 = xin + (size_t)b * C_DIM * PLANE;
    float* outrow = out + ((size_t)(b * C_DIM) * S_DIM + y) * S_DIM;

    const int xbase = threadIdx.x * 4;
    float res[C_DIM][4];

#pragma unroll
    for (int k = 0; k < 4; k++) {
        const int xc = xbase + k;

        // x-axis upsample map
        float fx = fmaxf(fmaf((float)xc, AXC, AXB), 0.0f);
        int   rx0 = (int)fx;
        float wrx = fx - (float)rx0;
        int   rx1 = min(rx0 + 1, G_DIM - 1);

        float gx0 = rowx[rx0], gx1 = rowx[rx1];
        float gy0 = rowy[rx0], gy1 = rowy[rx1];
        float gx = fmaf(wrx, gx1 - gx0, gx0);
        float gy = fmaf(wrx, gy1 - gy0, gy0);

        float lin_x = fmaf((float)xc, 2.0f / (float)(S_DIM - 1), -1.0f);
        float grid_x = fminf(fmaxf(gx + lin_x, -1.0f), 1.0f);
        float grid_y = fminf(fmaxf(gy + lin_y, -1.0f), 1.0f);

        // ix = ((grid+1)*S - 1)/2 = grid*512 + 511.5 ; ix in [-0.5, 1023.5]
        float ix = fmaf(grid_x, 0.5f * (float)S_DIM, 0.5f * (float)S_DIM - 0.5f);
        float iy = fmaf(grid_y, 0.5f * (float)S_DIM, 0.5f * (float)S_DIM - 0.5f);

        float fx0 = floorf(ix), fy0 = floorf(iy);
        int x0 = (int)fx0, y0 = (int)fy0;     // x0 in [-1,1023], y0 in [-1,1023]
        float wx = ix - fx0, wy = iy - fy0;

        // only two boundary cases per axis possible
        float wx0 = (x0 >= 0)         ? (1.0f - wx) : 0.0f;
        float wx1 = (x0 < S_DIM - 1)  ? wx          : 0.0f;
        float wy0 = (y0 >= 0)         ? (1.0f - wy) : 0.0f;
        float wy1 = (y0 < S_DIM - 1)  ? wy          : 0.0f;

        int cx0 = max(x0, 0);
        int cx1 = min(x0 + 1, S_DIM - 1);
        int cy0 = max(y0, 0);
        int cy1 = min(y0 + 1, S_DIM - 1);

        const float* r0 = img0 + cy0 * S_DIM;
        const float* r1 = img0 + cy1 * S_DIM;

#pragma unroll
        for (int c = 0; c < C_DIM; c++) {
            const int po = c * PLANE;
            float h0 = fmaf(r0[po + cx1], wx1, r0[po + cx0] * wx0);
            float h1 = fmaf(r1[po + cx1], wx1, r1[po + cx0] * wx0);
            res[c][k] = fmaf(h1, wy1, h0 * wy0);
        }
    }

#pragma unroll
    for (int c = 0; c < C_DIM; c++) {
        float4 v = make_float4(res[c][0], res[c][1], res[c][2], res[c][3]);
        *reinterpret_cast<float4*>(outrow + (size_t)c * PLANE + xbase) = v;
    }
}

extern "C" void kernel_launch(void* const* d_in, const int* in_sizes, int n_in,
                              void* d_out, int out_size) {
    const float* x        = (const float*)d_in[0];
    const float* offset_x = (const float*)d_in[1];
    const float* offset_y = (const float*)d_in[2];
    const float* weight   = (const float*)d_in[3];
    const void*  max_move = d_in[4];

    float* out = (float*)d_out;

    smooth_kernel<<<(B_DIM * 2 * G_DIM * G_DIM + 127) / 128, 128>>>(
        offset_x, offset_y, weight, max_move);

    dim3 grid(S_DIM, B_DIM);
    deform_kernel<<<grid, 256>>>(x, out);
}

// round 4
// speedup vs baseline: 1.2024x; 1.1462x over previous
#include <cuda_runtime.h>
#include <cstdint>

#define S_DIM 1024
#define G_DIM 10
#define F_DIM 5
#define B_DIM 8
#define C_DIM 3
#define KW (2 * F_DIM + 1)   // 11
#define PLANE (S_DIM * S_DIM)

// Smoothed, scaled, clipped offset field: [B, 2, G, G]
__device__ float g_field[B_DIM * 2 * G_DIM * G_DIM];

// ---------------------------------------------------------------------------
// Kernel 1: 11x11 gaussian conv (edge padding) on the 10x10 offset grids,
// then scale by max_offset and clip. 1600 threads — negligible.
// ---------------------------------------------------------------------------
__global__ void smooth_kernel(const float* __restrict__ off_x,
                              const float* __restrict__ off_y,
                              const float* __restrict__ weight,
                              const void* __restrict__ max_move_ptr) {
    int idx = blockIdx.x * blockDim.x + threadIdx.x;
    if (idx >= B_DIM * 2 * G_DIM * G_DIM) return;

    unsigned u = *(const unsigned*)max_move_ptr;
    int as_int = (int)u;
    float mm = (as_int >= -1000000 && as_int <= 1000000) ? (float)as_int
                                                         : __int_as_float(as_int);
    float max_offset = 2.0f * mm / (float)S_DIM;

    int j  = idx % G_DIM;
    int i  = (idx / G_DIM) % G_DIM;
    int ch = (idx / (G_DIM * G_DIM)) % 2;
    int b  = idx / (2 * G_DIM * G_DIM);

    const float* src = (ch == 0 ? off_x : off_y) + b * G_DIM * G_DIM;

    float acc = 0.0f;
#pragma unroll
    for (int ki = 0; ki < KW; ki++) {
        int pi = min(max(i + ki - F_DIM, 0), G_DIM - 1);
#pragma unroll
        for (int kj = 0; kj < KW; kj++) {
            int pj = min(max(j + kj - F_DIM, 0), G_DIM - 1);
            acc += src[pi * G_DIM + pj] * weight[ki * KW + kj];
        }
    }
    acc *= max_offset;
    acc = fminf(fmaxf(acc, -max_offset), max_offset);
    g_field[idx] = acc;
}

// ---------------------------------------------------------------------------
// Kernel 2: one block per (y, b) output row; 256 threads, 4 pixels each,
// pixels mapped warp-CONTIGUOUSLY (xc = tid + 256*k) so every warp-wide
// gather load spans ~128B (1-2 L1 lines) instead of 512B.
// Field y-interpolation hoisted to shared row buffers.
// ---------------------------------------------------------------------------
__global__ __launch_bounds__(256)
void deform_kernel(const float* __restrict__ xin, float* __restrict__ out) {
    const int y = blockIdx.x;
    const int b = blockIdx.y;

    __shared__ float rowx[G_DIM];
    __shared__ float rowy[G_DIM];

    // y-axis upsample map (block-uniform): src = max((y+0.5)*G/S - 0.5, 0)
    const float AXC = (float)G_DIM / (float)S_DIM;            // 0.009765625
    const float AXB = 0.5f * AXC - 0.5f;                      // -0.4951171875
    float fy = fmaxf(fmaf((float)y, AXC, AXB), 0.0f);
    int   ry0 = (int)fy;                 // fy >= 0, floor == trunc; max 9
    float wry = fy - (float)ry0;
    int   ry1 = min(ry0 + 1, G_DIM - 1);

    if (threadIdx.x < 2 * G_DIM) {
        int ch  = threadIdx.x / G_DIM;
        int col = threadIdx.x - ch * G_DIM;
        const float* f = g_field + (b * 2 + ch) * G_DIM * G_DIM;
        float v0 = f[ry0 * G_DIM + col];
        float v1 = f[ry1 * G_DIM + col];
        float v  = fmaf(wry, v1 - v0, v0);
        (ch == 0 ? rowx : rowy)[col] = v;
    }
    __syncthreads();

    const float lin_y = fmaf((float)y, 2.0f / (float)(S_DIM - 1), -1.0f);

    const float* img0 = xin + (size_t)b * C_DIM * PLANE;
    float* outrow = out + ((size_t)(b * C_DIM) * S_DIM + y) * S_DIM;

#pragma unroll
    for (int k = 0; k < 4; k++) {
        const int xc = threadIdx.x + 256 * k;   // warp-contiguous mapping

        // x-axis upsample map
        float fxs = fmaxf(fmaf((float)xc, AXC, AXB), 0.0f);
        int   rx0 = (int)fxs;
        float wrx = fxs - (float)rx0;
        int   rx1 = min(rx0 + 1, G_DIM - 1);

        float gx0 = rowx[rx0], gx1 = rowx[rx1];
        float gy0 = rowy[rx0], gy1 = rowy[rx1];
        float gx = fmaf(wrx, gx1 - gx0, gx0);
        float gy = fmaf(wrx, gy1 - gy0, gy0);

        float lin_x = fmaf((float)xc, 2.0f / (float)(S_DIM - 1), -1.0f);
        float grid_x = fminf(fmaxf(gx + lin_x, -1.0f), 1.0f);
        float grid_y = fminf(fmaxf(gy + lin_y, -1.0f), 1.0f);

        // ix = ((grid+1)*S - 1)/2 = grid*512 + 511.5 ; ix in [-0.5, 1023.5]
        float ix = fmaf(grid_x, 0.5f * (float)S_DIM, 0.5f * (float)S_DIM - 0.5f);
        float iy = fmaf(grid_y, 0.5f * (float)S_DIM, 0.5f * (float)S_DIM - 0.5f);

        float fx0 = floorf(ix), fy0 = floorf(iy);
        int x0 = (int)fx0, y0 = (int)fy0;     // x0 in [-1,1023], y0 in [-1,1023]
        float wx = ix - fx0, wy = iy - fy0;

        // only two boundary cases per axis possible
        float wx0 = (x0 >= 0)         ? (1.0f - wx) : 0.0f;
        float wx1 = (x0 < S_DIM - 1)  ? wx          : 0.0f;
        float wy0 = (y0 >= 0)         ? (1.0f - wy) : 0.0f;
        float wy1 = (y0 < S_DIM - 1)  ? wy          : 0.0f;

        int cx0 = max(x0, 0);
        int cx1 = min(x0 + 1, S_DIM - 1);
        int cy0 = max(y0, 0);
        int cy1 = min(y0 + 1, S_DIM - 1);

        const float* r0 = img0 + cy0 * S_DIM;
        const float* r1 = img0 + cy1 * S_DIM;

#pragma unroll
        for (int c = 0; c < C_DIM; c++) {
            const int po = c * PLANE;
            float h0 = fmaf(r0[po + cx1], wx1, r0[po + cx0] * wx0);
            float h1 = fmaf(r1[po + cx1], wx1, r1[po + cx0] * wx0);
            float v  = fmaf(h1, wy1, h0 * wy0);
            outrow[(size_t)c * PLANE + xc] = v;
        }
    }
}

extern "C" void kernel_launch(void* const* d_in, const int* in_sizes, int n_in,
                              void* d_out, int out_size) {
    const float* x        = (const float*)d_in[0];
    const float* offset_x = (const float*)d_in[1];
    const float* offset_y = (const float*)d_in[2];
    const float* weight   = (const float*)d_in[3];
    const void*  max_move = d_in[4];

    float* out = (float*)d_out;

    smooth_kernel<<<(B_DIM * 2 * G_DIM * G_DIM + 127) / 128, 128>>>(
        offset_x, offset_y, weight, max_move);

    dim3 grid(S_DIM, B_DIM);
    deform_kernel<<<grid, 256>>>(x, out);
}